// round 5
// baseline (speedup 1.0000x reference)
#include <cuda_runtime.h>

#define NTAGS 64
#define SOS_IDX 1
#define EOS_IDX 2
#define REF_TAG 3

static __device__ __forceinline__ unsigned long long pk2(float x, float y) {
    unsigned long long r;
    asm("mov.b64 %0, {%1, %2};" : "=l"(r) : "f"(x), "f"(y));
    return r;
}
static __device__ __forceinline__ void upk2(unsigned long long a, float &x, float &y) {
    asm("mov.b64 {%0, %1}, %2;" : "=f"(x), "=f"(y) : "l"(a));
}
static __device__ __forceinline__ unsigned long long fma2(unsigned long long a,
                                                          unsigned long long b,
                                                          unsigned long long c) {
    unsigned long long d;
    asm("fma.rn.f32x2 %0, %1, %2, %3;" : "=l"(d) : "l"(a), "l"(b), "l"(c));
    return d;
}
static __device__ __forceinline__ unsigned long long add2(unsigned long long a,
                                                          unsigned long long b) {
    unsigned long long d;
    asm("add.rn.f32x2 %0, %1, %2;" : "=l"(d) : "l"(a), "l"(b));
    return d;
}

__global__ void __launch_bounds__(128) crf_fwd_kernel(
    const float* __restrict__ h, const float* __restrict__ mask,
    const float* __restrict__ trans, float* __restrict__ out, int T)
{
    const int b = blockIdx.x;
    const int tid = threadIdx.x;
    const int w = tid >> 5;
    const int l = tid & 31;
    // two lanes per tag: lane l and lane l^16 (same warp) split the j-range
    const int tag  = w * 16 + (l & 15);
    const int half = l >> 4;            // 0: j in [0,32), 1: j in [32,64)

    __shared__ __align__(16) float sh_u[2][NTAGS];
    __shared__ float sh_red[4];

    // E2[k] = exp(trans[tag][jbase+2k..2k+1]) for this thread's j-half.
    // exp(-10000) underflows to exactly 0 -> masked transitions vanish.
    unsigned long long E2[16];
    {
        const float4* tr = reinterpret_cast<const float4*>(trans + tag * NTAGS + half * 32);
        #pragma unroll
        for (int k = 0; k < 8; k++) {
            float4 t4 = tr[k];
            E2[2 * k]     = pk2(__expf(t4.x), __expf(t4.y));
            E2[2 * k + 1] = pk2(__expf(t4.z), __expf(t4.w));
        }
    }
    const float eeos = __expf(trans[EOS_IDX * NTAGS + tag]);

    const float* hb = h + (size_t)b * T * NTAGS + tag;
    const float* mb = mask + (size_t)b * T;

    // raw prefetch buffers (depth 4): exp() applied 4 iterations after the load.
    float rawh[4], mbuf[4];
    #pragma unroll
    for (int k = 0; k < 4; k++) {
        int tp = (k < T) ? k : (T - 1);
        rawh[k] = hb[(size_t)tp * NTAGS];
        mbuf[k] = mb[tp];
    }

    // U(-1): 1 at SOS, 0 elsewhere.
    if (tid < NTAGS) sh_u[0][tid] = (tid == SOS_IDX) ? 1.0f : 0.0f;
    float myu = (tag == SOS_IDX) ? 1.0f : 0.0f;
    int Esum = 0;
    __syncthreads();

    #pragma unroll 4
    for (int t = 0; t < T; t++) {
        const float mcur = mbuf[t & 3];
        if (mcur == 0.0f) break;            // mask is a prefix of ones
        const float eh = __expf(rawh[t & 3]);  // operand loaded 4 iters ago
        {
            int tp = t + 4;
            tp = (tp < T) ? tp : (T - 1);   // SEL, branchless, always in-bounds
            rawh[t & 3] = hb[(size_t)tp * NTAGS];
            mbuf[t & 3] = mb[tp];
        }

        const float* up = sh_u[t & 1];
        float* un = sh_u[(t + 1) & 1];

        // power-of-two renormalizer from the reference tag (exact, ALU-only,
        // off the dot's critical path)
        const unsigned int ub = __float_as_uint(up[REF_TAG]);
        int e = (int)((ub >> 23) & 0xffu) - 127;
        e = (ub == 0u) ? 0 : e;             // t==0: uref is exactly 0
        const float scale = __uint_as_float((unsigned)(127 - e) << 23);
        Esum += e;
        const float es = eh * scale;

        // half-dot: this thread's 32 j's = 8 front-batched LDS.128 +
        // 16 packed f32x2 FMAs into 4 accumulators (chain depth 4)
        const float4* pv = reinterpret_cast<const float4*>(up) + half * 8;
        float4 pa[8];
        #pragma unroll
        for (int k = 0; k < 8; k++) pa[k] = pv[k];
        unsigned long long acc[4];
        #pragma unroll
        for (int k = 0; k < 8; k++) {
            const int a0 = (k & 1) * 2;
            unsigned long long lo = fma2(E2[2 * k],     pk2(pa[k].x, pa[k].y),
                                         (k < 2) ? 0ull : acc[a0]);
            unsigned long long hi = fma2(E2[2 * k + 1], pk2(pa[k].z, pa[k].w),
                                         (k < 2) ? 0ull : acc[a0 + 1]);
            acc[a0] = lo; acc[a0 + 1] = hi;
        }
        unsigned long long sA = add2(add2(acc[0], acc[2]), add2(acc[1], acc[3]));
        float vx, vy;
        upk2(sA, vx, vy);
        const float vhalf = vx + vy;

        // combine the two j-halves: partner lane is l^16 (same warp)
        const float vfull = vhalf + __shfl_xor_sync(0xffffffffu, vhalf, 16);

        const float u = es * vfull;         // U_tag(t), identical in both lanes
        un[tag] = u;                        // both lanes store same value
        myu = u;
        __syncthreads();                    // single barrier per step
    }

    // out[b] = Esum*ln2 + log( sum_i U_i * exp(trans[EOS,i]) )
    float term = (half == 0) ? myu * eeos : 0.0f;
    #pragma unroll
    for (int o = 16; o > 0; o >>= 1) term += __shfl_xor_sync(0xffffffffu, term, o);
    __syncthreads();
    if (l == 0) sh_red[w] = term;
    __syncthreads();
    if (tid == 0) {
        out[b] = (float)Esum * 0.6931471805599453f +
                 __logf((sh_red[0] + sh_red[1]) + (sh_red[2] + sh_red[3]));
    }
}

extern "C" void kernel_launch(void* const* d_in, const int* in_sizes, int n_in,
                              void* d_out, int out_size) {
    const float* h     = (const float*)d_in[0];   // [B, T, 64]
    const float* mask  = (const float*)d_in[1];   // [B, T]
    const float* trans = (const float*)d_in[2];   // [64, 64]
    float* out = (float*)d_out;                   // [B]
    const int B = out_size;
    const int T = in_sizes[1] / B;
    crf_fwd_kernel<<<B, 128>>>(h, mask, trans, out, T);
}

// round 6
// speedup vs baseline: 1.4260x; 1.4260x over previous
#include <cuda_runtime.h>

#define NTAGS 64
#define SOS_IDX 1
#define EOS_IDX 2
#define REF_TAG 3

static __device__ __forceinline__ unsigned long long pk2(float x, float y) {
    unsigned long long r;
    asm("mov.b64 %0, {%1, %2};" : "=l"(r) : "f"(x), "f"(y));
    return r;
}
static __device__ __forceinline__ void upk2(unsigned long long a, float &x, float &y) {
    asm("mov.b64 {%0, %1}, %2;" : "=f"(x), "=f"(y) : "l"(a));
}
static __device__ __forceinline__ unsigned long long fma2(unsigned long long a,
                                                          unsigned long long b,
                                                          unsigned long long c) {
    unsigned long long d;
    asm("fma.rn.f32x2 %0, %1, %2, %3;" : "=l"(d) : "l"(a), "l"(b), "l"(c));
    return d;
}
static __device__ __forceinline__ unsigned long long add2(unsigned long long a,
                                                          unsigned long long b) {
    unsigned long long d;
    asm("add.rn.f32x2 %0, %1, %2;" : "=l"(d) : "l"(a), "l"(b));
    return d;
}

__global__ void __launch_bounds__(NTAGS) crf_fwd_kernel(
    const float* __restrict__ h, const float* __restrict__ mask,
    const float* __restrict__ trans, float* __restrict__ out, int T)
{
    const int b = blockIdx.x;
    const int i = threadIdx.x;          // one thread per tag
    const int warp = i >> 5;
    const int lane = i & 31;

    __shared__ __align__(16) float sh_u[2][NTAGS];
    __shared__ float sh_red[2];

    // ---- len = sum(mask[b,:]) once (mask is a prefix of ones) ----
    const float* mb = mask + (size_t)b * T;
    float msum = 0.0f;
    {
        const float4* m4 = reinterpret_cast<const float4*>(mb);
        const int n4 = T >> 2;
        for (int k = i; k < n4; k += NTAGS) {
            float4 v = m4[k];
            msum += (v.x + v.y) + (v.z + v.w);
        }
        #pragma unroll
        for (int o = 16; o > 0; o >>= 1) msum += __shfl_xor_sync(0xffffffffu, msum, o);
        if (lane == 0) sh_red[warp] = msum;
    }

    // E[i][j] = exp(trans[i][j]) packed as f32x2 (constant over t).
    // exp(-10000) underflows to exactly 0 -> masked transitions vanish.
    unsigned long long E2[NTAGS / 2];
    {
        const float4* tr = reinterpret_cast<const float4*>(trans + i * NTAGS);
        #pragma unroll
        for (int k = 0; k < NTAGS / 4; k++) {
            float4 t4 = tr[k];
            E2[2 * k]     = pk2(__expf(t4.x), __expf(t4.y));
            E2[2 * k + 1] = pk2(__expf(t4.z), __expf(t4.w));
        }
    }
    const float eeos = __expf(trans[EOS_IDX * NTAGS + i]);

    const float* hb = h + (size_t)b * T * NTAGS + i;

    __syncthreads();
    const int len = (int)(sh_red[0] + sh_red[1] + 0.5f);   // 1 <= len <= T

    // raw prefetch buffers (depth 4)
    float rawh[4];
    #pragma unroll
    for (int k = 0; k < 4; k++) {
        int tp = (k < T) ? k : (T - 1);
        rawh[k] = hb[(size_t)tp * NTAGS];
    }

    // U(-1): 1 at SOS, 0 elsewhere.
    sh_u[0][i] = (i == SOS_IDX) ? 1.0f : 0.0f;
    float myu = (i == SOS_IDX) ? 1.0f : 0.0f;
    int Esum = 0;
    float ehcur = __expf(rawh[0]);      // exp computed one full step ahead
    __syncthreads();

    #pragma unroll 4
    for (int t = 0; t < len; t++) {
        // prefetch h for t+4 (always in-bounds via clamp) and exp for t+1:
        // both are independent of this step's exchange -> fully hidden.
        {
            int tp = t + 4;
            tp = (tp < T) ? tp : (T - 1);
            float fresh = hb[(size_t)tp * NTAGS];
            float ehnext = __expf(rawh[(t + 1) & 3]);   // loaded at t-3, ready
            rawh[t & 3] = fresh;
            // consume current, rotate next
            const float eh = ehcur;
            ehcur = ehnext;

            const float* up = sh_u[t & 1];
            float* un = sh_u[(t + 1) & 1];
            const float4* pv = reinterpret_cast<const float4*>(up);

            // w_i = dot(E_row_i, U_prev): two front-batched groups of 8 LDS.128,
            // 32 packed f32x2 FMAs into 8 independent accumulators.
            unsigned long long acc[8];
            float4 pa[8];
            #pragma unroll
            for (int k = 0; k < 8; k++) pa[k] = pv[k];          // j = 0..31
            // power-of-two renormalizer (exact, ALU-only, off the dot path)
            const unsigned int ub = __float_as_uint(up[REF_TAG]);
            int e = (int)((ub >> 23) & 0xffu) - 127;
            e = (ub == 0u) ? 0 : e;             // t==0: uref is exactly 0
            const float scale = __uint_as_float((unsigned)(127 - e) << 23);
            Esum += e;
            const float es = eh * scale;

            #pragma unroll
            for (int k = 0; k < 8; k++) {
                const int a0 = (k & 3) * 2;
                unsigned long long lo = fma2(E2[2 * k],     pk2(pa[k].x, pa[k].y),
                                             (k < 4) ? 0ull : acc[a0]);
                unsigned long long hi = fma2(E2[2 * k + 1], pk2(pa[k].z, pa[k].w),
                                             (k < 4) ? 0ull : acc[a0 + 1]);
                acc[a0] = lo; acc[a0 + 1] = hi;
            }
            #pragma unroll
            for (int k = 0; k < 8; k++) pa[k] = pv[k + 8];      // j = 32..63
            #pragma unroll
            for (int k = 0; k < 8; k++) {
                const int a0 = (k & 3) * 2;
                acc[a0]     = fma2(E2[2 * (k + 8)],     pk2(pa[k].x, pa[k].y), acc[a0]);
                acc[a0 + 1] = fma2(E2[2 * (k + 8) + 1], pk2(pa[k].z, pa[k].w), acc[a0 + 1]);
            }
            unsigned long long s01 = add2(acc[0], acc[2]);
            unsigned long long s23 = add2(acc[4], acc[6]);
            unsigned long long s45 = add2(acc[1], acc[3]);
            unsigned long long s67 = add2(acc[5], acc[7]);
            unsigned long long sA  = add2(add2(s01, s23), add2(s45, s67));
            float vx, vy;
            upk2(sA, vx, vy);
            const float w = vx + vy;

            const float u = es * w;             // U_i(t)
            un[i] = u;
            myu = u;
        }
        __syncthreads();                        // single barrier per step
    }

    // out[b] = Esum*ln2 + log( sum_i U_i * exp(trans[EOS,i]) )
    float term = myu * eeos;
    #pragma unroll
    for (int o = 16; o > 0; o >>= 1) term += __shfl_xor_sync(0xffffffffu, term, o);
    __syncthreads();                            // sh_red reuse safety
    if (lane == 0) sh_red[warp] = term;
    __syncthreads();
    if (i == 0) {
        out[b] = (float)Esum * 0.6931471805599453f + __logf(sh_red[0] + sh_red[1]);
    }
}

extern "C" void kernel_launch(void* const* d_in, const int* in_sizes, int n_in,
                              void* d_out, int out_size) {
    const float* h     = (const float*)d_in[0];   // [B, T, 64]
    const float* mask  = (const float*)d_in[1];   // [B, T]
    const float* trans = (const float*)d_in[2];   // [64, 64]
    float* out = (float*)d_out;                   // [B]
    const int B = out_size;
    const int T = in_sizes[1] / B;
    crf_fwd_kernel<<<B, NTAGS>>>(h, mask, trans, out, T);
}